// round 2
// baseline (speedup 1.0000x reference)
#include <cuda_runtime.h>
#include <cuda_bf16.h>

#define P 96
#define NN 9216            // P*P
#define CAP 2304           // shared box cache capacity (fits 48KB static smem)

// Scratch (device globals — no allocation allowed)
__device__ float  g_sc[NN];
__device__ float4 g_bx[NN];

// ---------------------------------------------------------------------------
// Kernel 1: zero output, decode boxes, compute stable descending rank by score,
// scatter (score, box) to rank slot.  rank(i) = #{j: s_j>s_i} + #{j<i: s_j==s_i}
// (validity s>0.9 is implied for anything ranked against a valid element).
// ---------------------------------------------------------------------------
__global__ void __launch_bounds__(256) k_decode_rank(
    const float* __restrict__ x, float* __restrict__ out, int out_size)
{
    __shared__ float s[NN];
    const int tid = threadIdx.x;
    const int gid = blockIdx.x * blockDim.x + tid;   // 0..9215 exactly
    const int nthr = gridDim.x * blockDim.x;

    // zero the (poisoned) output buffer
    for (int i = gid; i < out_size; i += nthr) out[i] = 0.0f;

    // stage all scores (x[0]) into shared
    for (int i = tid; i < NN; i += blockDim.x) s[i] = x[i];
    __syncthreads();

    const float p = s[gid];
    if (!(p > 0.9f)) return;

    // counting rank (float4 scan of shared)
    int rank = 0;
    const float4* s4 = reinterpret_cast<const float4*>(s);
    #pragma unroll 4
    for (int q = 0; q < NN / 4; ++q) {
        float4 v = s4[q];
        int b = q << 2;
        rank += (v.x > p) + ((v.x == p) && (b + 0 < gid));
        rank += (v.y > p) + ((v.y == p) && (b + 1 < gid));
        rank += (v.z > p) + ((v.z == p) && (b + 2 < gid));
        rank += (v.w > p) + ((v.w == p) && (b + 3 < gid));
    }

    // decode box (exactly mirroring the reference op order; no FMA contraction)
    const float fi = (float)(gid / P);
    const float fj = (float)(gid % P);
    const float x1v = x[1 * NN + gid];
    const float x2v = x[2 * NN + gid];
    const float x3v = x[3 * NN + gid];
    const float x4v = x[4 * NN + gid];
    const float bx = __fadd_rn(__fmul_rn(x1v, 16.0f), __fmul_rn(fi, 16.0f));
    const float by = __fadd_rn(__fmul_rn(x2v, 16.0f), __fmul_rn(fj, 16.0f));
    const float bw = __fmul_rn(x3v, 1536.0f);
    const float bh = __fmul_rn(x4v, 1536.0f);
    const float X1 = rintf(bx);
    const float Y1 = rintf(by);
    const float X2 = rintf(__fadd_rn(bw, bx));
    const float Y2 = rintf(__fadd_rn(bh, by));

    g_sc[rank] = p;
    g_bx[rank] = make_float4(X1, Y1, X2, Y2);
}

// ---------------------------------------------------------------------------
// Kernel 2: single-block greedy NMS over sorted ranks with skip-scan
// (barriers paid only per KEPT box, not per rank).
// ---------------------------------------------------------------------------
__global__ void __launch_bounds__(256) k_nms(
    const float* __restrict__ x, float* __restrict__ out, int out_size)
{
    __shared__ unsigned char sup[NN];
    __shared__ float4 sb[CAP];
    __shared__ int M_s;

    const int tid = threadIdx.x;
    const int nt  = blockDim.x;

    // count M = number of valid scores
    if (tid == 0) M_s = 0;
    __syncthreads();
    int c = 0;
    for (int i = tid; i < NN; i += nt) c += (x[i] > 0.9f);
    atomicAdd(&M_s, c);
    __syncthreads();
    const int M = M_s;

    for (int i = tid; i < M; i += nt) {
        sup[i] = 0;
        if (i < CAP) sb[i] = g_bx[i];
    }
    __syncthreads();

    const bool write_keeps = (out_size >= 6 * NN);

    int r = 0;
    while (r < M) {
        // skip suppressed ranks — sup[] is consistent across the block after the
        // last barrier and nobody writes during this scan, so no sync needed.
        while (r < M && sup[r]) ++r;
        if (r >= M) break;

        const float4 br = (r < CAP) ? sb[r] : g_bx[r];
        const float  ar = __fmul_rn(__fsub_rn(br.z, br.x), __fsub_rn(br.w, br.y));

        if (tid == 0) {
            out[r * 5 + 0] = g_sc[r];
            out[r * 5 + 1] = br.x;
            out[r * 5 + 2] = br.y;
            out[r * 5 + 3] = __fsub_rn(br.z, br.x);
            out[r * 5 + 4] = __fsub_rn(br.w, br.y);
            if (write_keeps) out[5 * NN + r] = 1.0f;
        }

        // suppress later boxes with IoU > 0.5 against box r
        for (int j = r + 1 + tid; j < M; j += nt) {
            if (sup[j]) continue;
            const float4 bj = (j < CAP) ? sb[j] : g_bx[j];
            const float ix1 = fmaxf(br.x, bj.x);
            const float iy1 = fmaxf(br.y, bj.y);
            const float ix2 = fminf(br.z, bj.z);
            const float iy2 = fminf(br.w, bj.w);
            const float iw = fmaxf(__fsub_rn(ix2, ix1), 0.0f);
            const float ih = fmaxf(__fsub_rn(iy2, iy1), 0.0f);
            const float inter = __fmul_rn(iw, ih);
            const float aj = __fmul_rn(__fsub_rn(bj.z, bj.x), __fsub_rn(bj.w, bj.y));
            const float uni = __fsub_rn(__fadd_rn(ar, aj), inter);
            if (uni > 0.0f && __fdiv_rn(inter, uni) > 0.5f) sup[j] = 1;
        }
        __syncthreads();   // one barrier per KEPT box only
        ++r;
    }
}

// ---------------------------------------------------------------------------
extern "C" void kernel_launch(void* const* d_in, const int* in_sizes, int n_in,
                              void* d_out, int out_size)
{
    const float* x  = (const float*)d_in[0];
    float* out = (float*)d_out;
    k_decode_rank<<<NN / 256, 256>>>(x, out, out_size);
    k_nms<<<1, 256>>>(x, out, out_size);
}

// round 3
// speedup vs baseline: 2.7266x; 2.7266x over previous
#include <cuda_runtime.h>
#include <cuda_bf16.h>

#define P 96
#define NN 9216
#define THR 0.9f
#define SCAP 5632                 // rank-kernel shared staging capacity
#define SMEM_BYTES 196608         // 192KB dynamic smem for mask staging
#define WMAX 144                  // ceil(NN/64)

// device-global scratch (no runtime allocation allowed)
__device__ int    g_cnt;
__device__ float  g_csc[NN];      // compacted scores
__device__ int    g_cid[NN];      // compacted original indices
__device__ float4 g_cbx[NN];      // compacted boxes (x1,y1,x2,y2)
__device__ float  g_sc[NN];       // rank-ordered scores
__device__ float4 g_bx[NN];       // rank-ordered boxes
__device__ unsigned long long g_mask[(size_t)NN * WMAX];  // suppression bitmask

// ---------------------------------------------------------------------------
// k1: zero output; compact valid (score>0.9) entries with decoded boxes.
// ---------------------------------------------------------------------------
__global__ void __launch_bounds__(256) k_compact(
    const float* __restrict__ x, float* __restrict__ out, int out_size)
{
    const int gid = blockIdx.x * 256 + threadIdx.x;      // exactly 0..NN-1

    for (int i = gid; i < out_size; i += NN) out[i] = 0.0f;

    const float s = x[gid];
    const bool valid = s > THR;
    const unsigned bal = __ballot_sync(0xffffffffu, valid);
    if (!valid) return;

    const int lane = threadIdx.x & 31;
    const int leader = __ffs(bal) - 1;
    int base = 0;
    if (lane == leader) base = atomicAdd(&g_cnt, __popc(bal));
    base = __shfl_sync(bal, base, leader);
    const int pos = base + __popc(bal & ((1u << lane) - 1u));

    // decode (mirror reference op order; forbid FMA contraction)
    const float fi = (float)(gid / P);
    const float fj = (float)(gid % P);
    const float bx = __fadd_rn(__fmul_rn(x[1 * NN + gid], 16.0f), __fmul_rn(fi, 16.0f));
    const float by = __fadd_rn(__fmul_rn(x[2 * NN + gid], 16.0f), __fmul_rn(fj, 16.0f));
    const float bw = __fmul_rn(x[3 * NN + gid], 1536.0f);
    const float bh = __fmul_rn(x[4 * NN + gid], 1536.0f);

    g_csc[pos] = s;
    g_cid[pos] = gid;
    g_cbx[pos] = make_float4(rintf(bx), rintf(by),
                             rintf(__fadd_rn(bw, bx)), rintf(__fadd_rn(bh, by)));
}

// ---------------------------------------------------------------------------
// k2: counting rank among the M compacted entries (stable: ties by orig id),
//     scatter to rank-ordered arrays.
// ---------------------------------------------------------------------------
__global__ void __launch_bounds__(256) k_rank()
{
    __shared__ float ss[SCAP];
    __shared__ int   si[SCAP];

    const int M = g_cnt;
    const bool use_sm = (M <= SCAP);
    if (use_sm) {
        for (int i = threadIdx.x; i < M; i += 256) { ss[i] = g_csc[i]; si[i] = g_cid[i]; }
    }
    __syncthreads();

    for (int t = blockIdx.x * 256 + threadIdx.x; t < M; t += gridDim.x * 256) {
        const float s  = use_sm ? ss[t] : g_csc[t];
        const int   id = use_sm ? si[t] : g_cid[t];
        int r = 0;
        for (int j = 0; j < M; ++j) {
            const float sj = use_sm ? ss[j] : g_csc[j];
            const int   ij = use_sm ? si[j] : g_cid[j];
            r += (sj > s) || ((sj == s) && (ij < id));
        }
        g_sc[r] = s;
        g_bx[r] = g_cbx[t];
    }
}

// ---------------------------------------------------------------------------
// k3: pairwise suppression bitmask. word (i,w): bit b set iff
//     IoU(box_i, box_{w*64+b}) > 0.5  (reference numerics, exact rn division).
// ---------------------------------------------------------------------------
__global__ void __launch_bounds__(256) k_mask()
{
    const int M = g_cnt;
    if (M == 0) return;
    const int W = (M + 63) >> 6;
    const long total = (long)M * W;

    for (long idx = (long)blockIdx.x * blockDim.x + threadIdx.x;
         idx < total; idx += (long)gridDim.x * blockDim.x)
    {
        const int i = (int)(idx / W);
        const int w = (int)(idx % W);
        const float4 bi = g_bx[i];
        const float  ai = __fmul_rn(__fsub_rn(bi.z, bi.x), __fsub_rn(bi.w, bi.y));

        const int j0 = w << 6;
        const int j1 = min(j0 + 64, M);
        unsigned long long bits = 0ull;
        for (int j = j0; j < j1; ++j) {
            const float4 bj = g_bx[j];
            const float ix1 = fmaxf(bi.x, bj.x);
            const float iy1 = fmaxf(bi.y, bj.y);
            const float ix2 = fminf(bi.z, bj.z);
            const float iy2 = fminf(bi.w, bj.w);
            const float iw = fmaxf(__fsub_rn(ix2, ix1), 0.0f);
            const float ih = fmaxf(__fsub_rn(iy2, iy1), 0.0f);
            const float inter = __fmul_rn(iw, ih);
            const float aj = __fmul_rn(__fsub_rn(bj.z, bj.x), __fsub_rn(bj.w, bj.y));
            const float uni = __fsub_rn(__fadd_rn(ai, aj), inter);
            if (uni > 0.0f && __fdiv_rn(inter, uni) > 0.5f)
                bits |= 1ull << (j - j0);
        }
        g_mask[(long)i * W + w] = bits;
    }
}

// ---------------------------------------------------------------------------
// k4: single-warp sequential greedy reduction over bitmask (mask in smem),
//     write kept rows, reset counter for the next graph replay.
// ---------------------------------------------------------------------------
extern __shared__ unsigned long long smask[];

__global__ void __launch_bounds__(256) k_reduce(float* __restrict__ out, int out_size)
{
    __shared__ unsigned long long removed[WMAX];

    const int M = g_cnt;
    if (M == 0) { if (threadIdx.x == 0) g_cnt = 0; return; }
    const int W = (M + 63) >> 6;
    const long words = (long)M * W;
    const bool use_sm = (words * 8 <= (long)SMEM_BYTES);

    if (use_sm)
        for (long t = threadIdx.x; t < words; t += 256) smask[t] = g_mask[t];
    for (int t = threadIdx.x; t < W; t += 256) removed[t] = 0ull;
    __syncthreads();

    if (threadIdx.x >= 32) return;     // warp 0 only from here
    const int lane = threadIdx.x;
    const unsigned long long* __restrict__ mask = use_sm ? smask : g_mask;
    const bool wk = (out_size >= 6 * NN);

    for (int w = 0; w < W; ++w) {
        unsigned long long cur = removed[w];
        const int nb = min(64, M - (w << 6));
        const unsigned long long vmask =
            (nb == 64) ? ~0ull : ((1ull << nb) - 1ull);

        for (;;) {
            const unsigned long long avail = ~cur & vmask;
            if (!avail) break;
            const int b = __ffsll(avail) - 1;
            const int i = (w << 6) + b;

            // keep i: OR its suppression row into the running removed state
            const long rowoff = (long)i * W;
            for (int t = lane; t < W; t += 32) removed[t] |= mask[rowoff + t];
            __syncwarp();
            cur = removed[w] | (1ull << b);   // self-bit in case of degenerate box

            if (lane == 0) {
                const float4 bi = g_bx[i];
                out[i * 5 + 0] = g_sc[i];
                out[i * 5 + 1] = bi.x;
                out[i * 5 + 2] = bi.y;
                out[i * 5 + 3] = __fsub_rn(bi.z, bi.x);
                out[i * 5 + 4] = __fsub_rn(bi.w, bi.y);
                if (wk) out[5 * NN + i] = 1.0f;
            }
        }
    }
    if (lane == 0) g_cnt = 0;          // deterministic state for next replay
}

// ---------------------------------------------------------------------------
extern "C" void kernel_launch(void* const* d_in, const int* in_sizes, int n_in,
                              void* d_out, int out_size)
{
    const float* x = (const float*)d_in[0];
    float* out = (float*)d_out;

    cudaFuncSetAttribute(k_reduce, cudaFuncAttributeMaxDynamicSharedMemorySize,
                         SMEM_BYTES);

    k_compact<<<NN / 256, 256>>>(x, out, out_size);
    k_rank<<<36, 256>>>();
    k_mask<<<256, 256>>>();
    k_reduce<<<1, 256, SMEM_BYTES>>>(out, out_size);
}

// round 5
// speedup vs baseline: 6.7181x; 2.4639x over previous
#include <cuda_runtime.h>
#include <cuda_bf16.h>
#include <cstdint>

#define P 96
#define NN 9216
#define THR 0.9f
#define SCAP 5632
#define W32MAX 288                    // ceil(NN/32)
#define SMEM_BYTES 163840             // 160KB dynamic smem for mask staging
#define FULLM 0xffffffffu

// device-global scratch (no runtime allocation allowed)
__device__ int      g_cnt;
__device__ float    g_csc[NN];
__device__ int      g_cid[NN];
__device__ float4   g_cbx[NN];
__device__ float    g_sc[NN];
__device__ float4   g_bx[NN];
__device__ uint32_t g_mask32[(size_t)NN * W32MAX];

// ---------------------------------------------------------------------------
// k1: zero output; compact valid (score>0.9) entries with decoded boxes.
// ---------------------------------------------------------------------------
__global__ void __launch_bounds__(256) k_compact(
    const float* __restrict__ x, float* __restrict__ out, int out_size)
{
    const int gid = blockIdx.x * 256 + threadIdx.x;      // exactly 0..NN-1
    for (int i = gid; i < out_size; i += NN) out[i] = 0.0f;

    const float s = x[gid];
    const bool valid = s > THR;
    const unsigned bal = __ballot_sync(FULLM, valid);
    if (!valid) return;

    const int lane = threadIdx.x & 31;
    const int leader = __ffs(bal) - 1;
    int base = 0;
    if (lane == leader) base = atomicAdd(&g_cnt, __popc(bal));
    base = __shfl_sync(bal, base, leader);
    const int pos = base + __popc(bal & ((1u << lane) - 1u));

    const float fi = (float)(gid / P);
    const float fj = (float)(gid % P);
    const float bx = __fadd_rn(__fmul_rn(x[1 * NN + gid], 16.0f), __fmul_rn(fi, 16.0f));
    const float by = __fadd_rn(__fmul_rn(x[2 * NN + gid], 16.0f), __fmul_rn(fj, 16.0f));
    const float bw = __fmul_rn(x[3 * NN + gid], 1536.0f);
    const float bh = __fmul_rn(x[4 * NN + gid], 1536.0f);

    g_csc[pos] = s;
    g_cid[pos] = gid;
    g_cbx[pos] = make_float4(rintf(bx), rintf(by),
                             rintf(__fadd_rn(bw, bx)), rintf(__fadd_rn(bh, by)));
}

// ---------------------------------------------------------------------------
// k2: counting rank among compacted entries (stable via original id tiebreak).
// ---------------------------------------------------------------------------
__global__ void __launch_bounds__(256) k_rank()
{
    __shared__ float ss[SCAP];
    __shared__ int   si[SCAP];

    const int M = g_cnt;
    const bool use_sm = (M <= SCAP);
    if (use_sm)
        for (int i = threadIdx.x; i < M; i += 256) { ss[i] = g_csc[i]; si[i] = g_cid[i]; }
    __syncthreads();

    for (int t = blockIdx.x * 256 + threadIdx.x; t < M; t += gridDim.x * 256) {
        const float s  = use_sm ? ss[t] : g_csc[t];
        const int   id = use_sm ? si[t] : g_cid[t];
        int r = 0;
        for (int j = 0; j < M; ++j) {
            const float sj = use_sm ? ss[j] : g_csc[j];
            const int   ij = use_sm ? si[j] : g_cid[j];
            r += (sj > s) || ((sj == s) && (ij < id));
        }
        g_sc[r] = s;
        g_bx[r] = g_cbx[t];
    }
}

// ---------------------------------------------------------------------------
// k3: 32-bit suppression mask, one block per row i, one thread per word.
// ---------------------------------------------------------------------------
__global__ void __launch_bounds__(32) k_mask()
{
    const int M = g_cnt;
    const int i = blockIdx.x;
    if (i >= M) return;
    const int W = (M + 31) >> 5;

    const float4 bi = g_bx[i];
    const float  ai = __fmul_rn(__fsub_rn(bi.z, bi.x), __fsub_rn(bi.w, bi.y));

    for (int w = threadIdx.x; w < W; w += 32) {
        const int j0 = w << 5;
        const int j1 = min(j0 + 32, M);
        uint32_t bits = 0u;
        for (int j = j0; j < j1; ++j) {
            const float4 bj = g_bx[j];
            const float ix1 = fmaxf(bi.x, bj.x);
            const float iy1 = fmaxf(bi.y, bj.y);
            const float ix2 = fminf(bi.z, bj.z);
            const float iy2 = fminf(bi.w, bj.w);
            const float iw = fmaxf(__fsub_rn(ix2, ix1), 0.0f);
            const float ih = fmaxf(__fsub_rn(iy2, iy1), 0.0f);
            const float inter = __fmul_rn(iw, ih);
            const float aj = __fmul_rn(__fsub_rn(bj.z, bj.x), __fsub_rn(bj.w, bj.y));
            const float uni = __fsub_rn(__fadd_rn(ai, aj), inter);
            if (uni > 0.0f && __fdiv_rn(inter, uni) > 0.5f)
                bits |= 1u << (j - j0);
        }
        g_mask32[i * W + w] = bits;
    }
}

// ---------------------------------------------------------------------------
// k4: greedy reduction. Fast path (M<=1024): removed bitvector in registers
// (1 word/lane), next-keep via redux.min (UNSIGNED sentinel — fixed), row
// prefetch (i+1) hides the LDS. Output rows written by all 256 threads after.
// ---------------------------------------------------------------------------
extern __shared__ uint32_t sm32[];

__global__ void __launch_bounds__(256) k_reduce(float* __restrict__ out, int out_size)
{
    __shared__ int s_keep[1024];
    __shared__ int s_nk;
    __shared__ uint32_t s_rm[W32MAX];   // slow-path only

    const int tid = threadIdx.x;
    const int M = g_cnt;
    if (M == 0) { if (tid == 0) g_cnt = 0; return; }
    const int W = (M + 31) >> 5;
    const int words = M * W;
    const bool fits = ((size_t)words * 4u <= (size_t)SMEM_BYTES);
    const bool wk = (out_size >= 6 * NN);

    if (fits)
        for (int t = tid; t < words; t += 256) sm32[t] = g_mask32[t];
    if (tid == 0) s_nk = 0;
    __syncthreads();

    if (W <= 32) {
        if (tid < 32) {
            const uint32_t* __restrict__ mrow = fits ? sm32 : g_mask32;
            const int lane = tid;
            const int nval = M - (lane << 5);
            uint32_t rem = (nval >= 32) ? 0u : ((nval <= 0) ? ~0u : (~0u << nval));

            int nk = 0;
            uint32_t avail = ~rem;
            unsigned idx = avail ? (unsigned)((lane << 5) + __ffs(avail) - 1) : FULLM;
            unsigned im = __reduce_min_sync(FULLM, idx);   // FULLM sentinel = done
            uint32_t pre = 0u; int pre_i = -1;

            while (im < (unsigned)M) {
                const int i = (int)im;
                if (lane == 0) s_keep[nk] = i;
                ++nk;
                uint32_t row = (i == pre_i) ? pre
                             : ((lane < W) ? mrow[i * W + lane] : 0u);
                const uint32_t self = (lane == (i >> 5)) ? (1u << (i & 31)) : 0u;
                rem |= row | self;
                // prefetch the most likely next keep (i+1)
                pre_i = i + 1;
                pre = (pre_i < M && lane < W) ? mrow[pre_i * W + lane] : 0u;

                avail = ~rem;
                idx = avail ? (unsigned)((lane << 5) + __ffs(avail) - 1) : FULLM;
                im = __reduce_min_sync(FULLM, idx);
            }
            if (lane == 0) s_nk = nk;
        }
    } else {
        // generic scalar fallback (not expected for this input scale)
        for (int t = tid; t < W; t += 256) s_rm[t] = 0u;
        __syncthreads();
        if (tid == 0) {
            for (int i = 0; i < M; ++i) {
                if ((s_rm[i >> 5] >> (i & 31)) & 1u) continue;
                const float4 bi = g_bx[i];
                out[i * 5 + 0] = g_sc[i];
                out[i * 5 + 1] = bi.x;
                out[i * 5 + 2] = bi.y;
                out[i * 5 + 3] = __fsub_rn(bi.z, bi.x);
                out[i * 5 + 4] = __fsub_rn(bi.w, bi.y);
                if (wk) out[5 * NN + i] = 1.0f;
                for (int t = 0; t < W; ++t) s_rm[t] |= g_mask32[i * W + t];
                s_rm[i >> 5] |= 1u << (i & 31);
            }
        }
    }
    __syncthreads();

    if (W <= 32) {
        const int nk = s_nk;
        for (int k = tid; k < nk; k += 256) {
            const int i = s_keep[k];
            const float4 bi = g_bx[i];
            out[i * 5 + 0] = g_sc[i];
            out[i * 5 + 1] = bi.x;
            out[i * 5 + 2] = bi.y;
            out[i * 5 + 3] = __fsub_rn(bi.z, bi.x);
            out[i * 5 + 4] = __fsub_rn(bi.w, bi.y);
            if (wk) out[5 * NN + i] = 1.0f;
        }
    }
    if (tid == 0) g_cnt = 0;   // deterministic state for next graph replay
}

// ---------------------------------------------------------------------------
extern "C" void kernel_launch(void* const* d_in, const int* in_sizes, int n_in,
                              void* d_out, int out_size)
{
    const float* x = (const float*)d_in[0];
    float* out = (float*)d_out;

    cudaFuncSetAttribute(k_reduce, cudaFuncAttributeMaxDynamicSharedMemorySize,
                         SMEM_BYTES);

    k_compact<<<NN / 256, 256>>>(x, out, out_size);
    k_rank<<<36, 256>>>();
    k_mask<<<NN, 32>>>();
    k_reduce<<<1, 256, SMEM_BYTES>>>(out, out_size);
}

// round 6
// speedup vs baseline: 9.3716x; 1.3950x over previous
#include <cuda_runtime.h>
#include <cuda_bf16.h>
#include <cstdint>

#define P 96
#define NN 9216
#define THR 0.9f
#define SCAP 5632
#define WSMAX 33                      // max padded row stride (W<=32 -> WS<=33)
#define SMEM_BYTES 163840             // 160KB dynamic smem for mask staging
#define FULLM 0xffffffffu

// device-global scratch (no runtime allocation allowed)
__device__ int      g_cnt;
__device__ float    g_csc[NN];
__device__ int      g_cid[NN];
__device__ float4   g_cbx[NN];
__device__ float    g_sc[NN];
__device__ float4   g_bx[NN];
__device__ __align__(16) uint32_t g_mask32[(size_t)1056 * WSMAX + NN]; // fast path 1024*33; slack for fallback sizing

// ---------------------------------------------------------------------------
// k1: zero output; compact valid (score>0.9) entries with decoded boxes.
// ---------------------------------------------------------------------------
__global__ void __launch_bounds__(256) k_compact(
    const float* __restrict__ x, float* __restrict__ out, int out_size)
{
    const int gid = blockIdx.x * 256 + threadIdx.x;      // exactly 0..NN-1
    for (int i = gid; i < out_size; i += NN) out[i] = 0.0f;

    const float s = x[gid];
    const bool valid = s > THR;
    const unsigned bal = __ballot_sync(FULLM, valid);
    if (!valid) return;

    const int lane = threadIdx.x & 31;
    const int leader = __ffs(bal) - 1;
    int base = 0;
    if (lane == leader) base = atomicAdd(&g_cnt, __popc(bal));
    base = __shfl_sync(bal, base, leader);
    const int pos = base + __popc(bal & ((1u << lane) - 1u));

    const float fi = (float)(gid / P);
    const float fj = (float)(gid % P);
    const float bx = __fadd_rn(__fmul_rn(x[1 * NN + gid], 16.0f), __fmul_rn(fi, 16.0f));
    const float by = __fadd_rn(__fmul_rn(x[2 * NN + gid], 16.0f), __fmul_rn(fj, 16.0f));
    const float bw = __fmul_rn(x[3 * NN + gid], 1536.0f);
    const float bh = __fmul_rn(x[4 * NN + gid], 1536.0f);

    g_csc[pos] = s;
    g_cid[pos] = gid;
    g_cbx[pos] = make_float4(rintf(bx), rintf(by),
                             rintf(__fadd_rn(bw, bx)), rintf(__fadd_rn(bh, by)));
}

// ---------------------------------------------------------------------------
// k2: counting rank among compacted entries (stable via original id tiebreak).
// ---------------------------------------------------------------------------
__global__ void __launch_bounds__(256) k_rank()
{
    __shared__ float ss[SCAP];
    __shared__ int   si[SCAP];

    const int M = g_cnt;
    const bool use_sm = (M <= SCAP);
    if (use_sm)
        for (int i = threadIdx.x; i < M; i += 256) { ss[i] = g_csc[i]; si[i] = g_cid[i]; }
    __syncthreads();

    for (int t = blockIdx.x * 256 + threadIdx.x; t < M; t += gridDim.x * 256) {
        const float s  = use_sm ? ss[t] : g_csc[t];
        const int   id = use_sm ? si[t] : g_cid[t];
        int r = 0;
        for (int j = 0; j < M; ++j) {
            const float sj = use_sm ? ss[j] : g_csc[j];
            const int   ij = use_sm ? si[j] : g_cid[j];
            r += (sj > s) || ((sj == s) && (ij < id));
        }
        g_sc[r] = s;
        g_bx[r] = g_cbx[t];
    }
}

// ---------------------------------------------------------------------------
// k3: 32-bit suppression mask, warp per row (grid-stride), odd row stride WS.
// ---------------------------------------------------------------------------
__global__ void __launch_bounds__(256) k_mask()
{
    const int M = g_cnt;
    if (M == 0) return;
    const int W  = (M + 31) >> 5;
    const int WS = W | 1;                                 // odd stride
    const int lane = threadIdx.x & 31;
    const int wg   = (blockIdx.x * 256 + threadIdx.x) >> 5;
    const int nwg  = (gridDim.x * 256) >> 5;

    for (int i = wg; i < M; i += nwg) {
        const float4 bi = g_bx[i];
        const float  ai = __fmul_rn(__fsub_rn(bi.z, bi.x), __fsub_rn(bi.w, bi.y));
        for (int w = lane; w < W; w += 32) {
            const int j0 = w << 5;
            const int j1 = min(j0 + 32, M);
            uint32_t bits = 0u;
            for (int j = j0; j < j1; ++j) {
                const float4 bj = g_bx[j];
                const float ix1 = fmaxf(bi.x, bj.x);
                const float iy1 = fmaxf(bi.y, bj.y);
                const float ix2 = fminf(bi.z, bj.z);
                const float iy2 = fminf(bi.w, bj.w);
                const float iw = fmaxf(__fsub_rn(ix2, ix1), 0.0f);
                const float ih = fmaxf(__fsub_rn(iy2, iy1), 0.0f);
                const float inter = __fmul_rn(iw, ih);
                const float aj = __fmul_rn(__fsub_rn(bj.z, bj.x), __fsub_rn(bj.w, bj.y));
                const float uni = __fsub_rn(__fadd_rn(ai, aj), inter);
                if (uni > 0.0f && __fdiv_rn(inter, uni) > 0.5f)
                    bits |= 1u << (j - j0);
            }
            g_mask32[i * WS + w] = bits;
        }
    }
}

// ---------------------------------------------------------------------------
// k4: greedy reduction, word-at-a-time.
//   Per 32-box word: Jacobi fixpoint on the 32x32 diagonal block resolves all
//   intra-word greedy decisions with ~2 redux.or ops; then kept rows are OR'd
//   into the lane-distributed removed bitvector (x4 unrolled, pipelined LDS).
// ---------------------------------------------------------------------------
extern __shared__ uint32_t sm32[];

__global__ void __launch_bounds__(256) k_reduce(float* __restrict__ out, int out_size)
{
    __shared__ uint32_t s_keepw[32];
    __shared__ uint32_t s_rm[WSMAX * 32];  // slow-path removed bits (generous)

    const int tid = threadIdx.x;
    const int M = g_cnt;
    if (M == 0) { if (tid == 0) g_cnt = 0; return; }
    const int W  = (M + 31) >> 5;
    const int WS = W | 1;
    const int words = M * WS;
    const bool fits = ((size_t)words * 4u <= (size_t)SMEM_BYTES);
    const bool wk = (out_size >= 6 * NN);

    if (fits) {
        // vectorized staging
        const uint4* __restrict__ src4 = reinterpret_cast<const uint4*>(g_mask32);
        uint4* dst4 = reinterpret_cast<uint4*>(sm32);
        const int n4 = words >> 2;
        for (int t = tid; t < n4; t += 256) dst4[t] = src4[t];
        for (int t = (n4 << 2) + tid; t < words; t += 256) sm32[t] = g_mask32[t];
    }
    __syncthreads();

    if (W <= 32) {
        if (tid < 32) {
            const uint32_t* __restrict__ mrow = fits ? sm32 : g_mask32;
            const int lane = tid;
            const uint32_t above = ~((2u << lane) - 1u);   // bits strictly > lane
            uint32_t rem = 0u;

            for (int w = 0; w < W; ++w) {
                const int base = w << 5;
                const int nval = M - base;
                const uint32_t vmask = (nval >= 32) ? ~0u : ((1u << nval) - 1u);
                const uint32_t rem_w = __shfl_sync(FULLM, rem, w);
                const uint32_t cand = ~rem_w & vmask;

                // diagonal block: lane b = row (base+b)'s word w, later-bits only
                const int irow = base + lane;
                uint32_t d = (irow < M) ? (mrow[irow * WS + w] & above) : 0u;

                // Jacobi fixpoint -> exact greedy decisions for this word
                uint32_t kept = cand;
                for (;;) {
                    const uint32_t contrib = ((kept >> lane) & 1u) ? d : 0u;
                    const uint32_t sup = __reduce_or_sync(FULLM, contrib);
                    const uint32_t kept2 = cand & ~sup;
                    if (kept2 == kept) break;
                    kept = kept2;
                }
                if (lane == 0) s_keepw[w] = kept;

                // OR kept rows into removed state (x4 unrolled, pipelined)
                uint32_t km = kept;
                while (km) {
                    const int b0 = __ffs(km) - 1; km &= km - 1;
                    int b1 = -1, b2 = -1, b3 = -1;
                    if (km) { b1 = __ffs(km) - 1; km &= km - 1;
                        if (km) { b2 = __ffs(km) - 1; km &= km - 1;
                            if (km) { b3 = __ffs(km) - 1; km &= km - 1; } } }
                    uint32_t r0 = 0u, r1 = 0u, r2 = 0u, r3 = 0u;
                    if (lane < W) {
                        r0 = mrow[(base + b0) * WS + lane];
                        if (b1 >= 0) r1 = mrow[(base + b1) * WS + lane];
                        if (b2 >= 0) r2 = mrow[(base + b2) * WS + lane];
                        if (b3 >= 0) r3 = mrow[(base + b3) * WS + lane];
                    }
                    rem |= (r0 | r1) | (r2 | r3);
                }
            }
        }
    } else {
        // generic scalar fallback (M > 1024; not expected here)
        for (int t = tid; t < W; t += 256) s_rm[t] = 0u;
        __syncthreads();
        if (tid == 0) {
            for (int i = 0; i < M; ++i) {
                if ((s_rm[i >> 5] >> (i & 31)) & 1u) continue;
                const float4 bi = g_bx[i];
                out[i * 5 + 0] = g_sc[i];
                out[i * 5 + 1] = bi.x;
                out[i * 5 + 2] = bi.y;
                out[i * 5 + 3] = __fsub_rn(bi.z, bi.x);
                out[i * 5 + 4] = __fsub_rn(bi.w, bi.y);
                if (wk) out[5 * NN + i] = 1.0f;
                for (int t = 0; t < W; ++t) s_rm[t] |= g_mask32[i * WS + t];
                s_rm[i >> 5] |= 1u << (i & 31);
            }
        }
    }
    __syncthreads();

    if (W <= 32) {
        for (int i = tid; i < M; i += 256) {
            if ((s_keepw[i >> 5] >> (i & 31)) & 1u) {
                const float4 bi = g_bx[i];
                out[i * 5 + 0] = g_sc[i];
                out[i * 5 + 1] = bi.x;
                out[i * 5 + 2] = bi.y;
                out[i * 5 + 3] = __fsub_rn(bi.z, bi.x);
                out[i * 5 + 4] = __fsub_rn(bi.w, bi.y);
                if (wk) out[5 * NN + i] = 1.0f;
            }
        }
    }
    if (tid == 0) g_cnt = 0;   // deterministic state for next graph replay
}

// ---------------------------------------------------------------------------
extern "C" void kernel_launch(void* const* d_in, const int* in_sizes, int n_in,
                              void* d_out, int out_size)
{
    const float* x = (const float*)d_in[0];
    float* out = (float*)d_out;

    cudaFuncSetAttribute(k_reduce, cudaFuncAttributeMaxDynamicSharedMemorySize,
                         SMEM_BYTES);

    k_compact<<<NN / 256, 256>>>(x, out, out_size);
    k_rank<<<36, 256>>>();
    k_mask<<<148, 256>>>();
    k_reduce<<<1, 256, SMEM_BYTES>>>(out, out_size);
}

// round 7
// speedup vs baseline: 10.8952x; 1.1626x over previous
#include <cuda_runtime.h>
#include <cuda_bf16.h>
#include <cstdint>

#define P     96
#define NN    9216
#define THR   0.9f
#define MAXM  1024                 // fast-path capacity (observed M ~ 922)
#define WSM   33                   // padded row stride for W<=32
#define FULLM 0xffffffffu
#define GRID  148
#define BLK   256
#define NTHR  (GRID * BLK)

// device-global scratch (no runtime allocation allowed)
__device__ int      g_cnt;
__device__ int      g_bar_cnt;
__device__ volatile int g_bar_flag;
__device__ int      g_rank[NN];
__device__ float    g_csc[NN];
__device__ int      g_cid[NN];
__device__ float4   g_cbx[NN];
__device__ float    g_sc[NN];
__device__ float4   g_bx[NN];
__device__ uint32_t g_mask32[MAXM * WSM];

// grid-wide barrier: all GRID blocks co-resident (GRID <= SM count) -> safe.
__device__ __forceinline__ void gbar(int phase)
{
    __syncthreads();
    if (threadIdx.x == 0) {
        __threadfence();
        if (atomicAdd(&g_bar_cnt, 1) == GRID - 1) {
            g_bar_cnt = 0;
            __threadfence();
            g_bar_flag = phase;
        } else {
            while (g_bar_flag < phase) { }
            __threadfence();
        }
    }
    __syncthreads();
}

__device__ __forceinline__ bool iou_gt(const float4 bi, const float ai, const float4 bj)
{
    const float ix1 = fmaxf(bi.x, bj.x);
    const float iy1 = fmaxf(bi.y, bj.y);
    const float ix2 = fminf(bi.z, bj.z);
    const float iy2 = fminf(bi.w, bj.w);
    const float iw = fmaxf(__fsub_rn(ix2, ix1), 0.0f);
    const float ih = fmaxf(__fsub_rn(iy2, iy1), 0.0f);
    const float inter = __fmul_rn(iw, ih);
    const float aj = __fmul_rn(__fsub_rn(bj.z, bj.x), __fsub_rn(bj.w, bj.y));
    const float uni = __fsub_rn(__fadd_rn(ai, aj), inter);
    return (uni > 0.0f) && (__fdiv_rn(inter, uni) > 0.5f);
}

__global__ void __launch_bounds__(BLK) k_all(
    const float* __restrict__ x, float* __restrict__ out, int out_size)
{
    __shared__ uint32_t sdiag[32 * 32];
    __shared__ uint32_t s_keepw[32];
    __shared__ uint32_t s_kb[NN / 32];       // slow-path kept bitmap

    const int tid  = threadIdx.x;
    const int gtid = blockIdx.x * BLK + tid;
    const int lane = tid & 31;

    // ---------------- phase 0: zero output/ranks, compact valid boxes -------
    for (int i = gtid; i < out_size; i += NTHR) out[i] = 0.0f;
    for (int i = gtid; i < NN; i += NTHR) g_rank[i] = 0;

    if (gtid < NN) {
        const float s = x[gtid];
        const bool valid = s > THR;
        const unsigned bal = __ballot_sync(FULLM, valid);
        if (valid) {
            const int leader = __ffs(bal) - 1;
            int base = 0;
            if (lane == leader) base = atomicAdd(&g_cnt, __popc(bal));
            base = __shfl_sync(bal, base, leader);
            const int pos = base + __popc(bal & ((1u << lane) - 1u));

            const float fi = (float)(gtid / P);
            const float fj = (float)(gtid % P);
            const float bx = __fadd_rn(__fmul_rn(x[1 * NN + gtid], 16.0f), __fmul_rn(fi, 16.0f));
            const float by = __fadd_rn(__fmul_rn(x[2 * NN + gtid], 16.0f), __fmul_rn(fj, 16.0f));
            const float bw = __fmul_rn(x[3 * NN + gtid], 1536.0f);
            const float bh = __fmul_rn(x[4 * NN + gtid], 1536.0f);

            g_csc[pos] = s;
            g_cid[pos] = gtid;
            g_cbx[pos] = make_float4(rintf(bx), rintf(by),
                                     rintf(__fadd_rn(bw, bx)), rintf(__fadd_rn(bh, by)));
        }
    }
    gbar(1);

    // ---------------- phase 1: counting rank (stable: score desc, id asc) ---
    const int M = g_cnt;
    if (M > 0 && M <= MAXM) {
        // j-split: 1024 t-slots x 37 j-chunks across all 37888 threads
        const int t = gtid & 1023;
        const int chunk = gtid >> 10;                 // 0..36
        const int C = (M + 36) / 37;
        const int j0 = chunk * C;
        const int j1 = min(j0 + C, M);
        if (t < M && j0 < j1) {
            const float s = g_csc[t];
            const int  id = g_cid[t];
            int r = 0;
            #pragma unroll 4
            for (int j = j0; j < j1; ++j) {
                const float sj = g_csc[j];
                const int   ij = g_cid[j];
                r += (sj > s) || ((sj == s) && (ij < id));
            }
            if (r) atomicAdd(&g_rank[t], r);
        }
    } else if (M > MAXM) {
        for (int t = gtid; t < M; t += NTHR) {
            const float s = g_csc[t];
            const int  id = g_cid[t];
            int r = 0;
            for (int j = 0; j < M; ++j) {
                const float sj = g_csc[j];
                const int   ij = g_cid[j];
                r += (sj > s) || ((sj == s) && (ij < id));
            }
            g_rank[t] = r;
        }
    }
    gbar(2);

    // ---------------- phase 2: scatter into rank order ----------------------
    for (int t = gtid; t < M; t += NTHR) {
        const int r = g_rank[t];
        g_sc[r] = g_csc[t];
        g_bx[r] = g_cbx[t];
    }
    gbar(3);

    // ---------------- phase 3: suppression mask (lane = bit, ballot) --------
    if (M > 0 && M <= MAXM) {
        const int W  = (M + 31) >> 5;
        const int WS = W | 1;
        const int wg = gtid >> 5;
        for (int i = wg; i < M; i += NTHR / 32) {
            const float4 bi = g_bx[i];
            const float  ai = __fmul_rn(__fsub_rn(bi.z, bi.x), __fsub_rn(bi.w, bi.y));
            uint32_t myword = 0u;
            for (int w = 0; w < W; ++w) {
                const int j = (w << 5) + lane;
                bool pred = false;
                if (j < M) pred = iou_gt(bi, ai, g_bx[j]);
                const uint32_t word = __ballot_sync(FULLM, pred);
                if (lane == w) myword = word;
            }
            if (lane < W) g_mask32[i * WS + lane] = myword;
        }
    }
    gbar(4);

    // ---------------- phase 4: greedy reduce (block 0 only) -----------------
    if (blockIdx.x != 0) return;
    const bool wk = (out_size >= 6 * NN);

    if (M > 0 && M <= MAXM) {
        const int W  = (M + 31) >> 5;
        const int WS = W | 1;

        // stage diagonal 32x32 blocks (word w of row idx, idx>>5 == w)
        for (int idx = tid; idx < (W << 5); idx += BLK)
            sdiag[idx] = (idx < M) ? g_mask32[idx * WS + (idx >> 5)] : 0u;
        __syncthreads();

        if (tid < 32) {
            const uint32_t above = ~((2u << lane) - 1u);   // bits strictly > lane
            uint32_t rem = 0u;

            for (int w = 0; w < W; ++w) {
                const int base = w << 5;

                // issue all 32 coalesced row loads early (overlap with Jacobi)
                uint32_t r[32];
                #pragma unroll
                for (int b = 0; b < 32; ++b)
                    r[b] = (lane < W) ? g_mask32[(base + b) * WS + lane] : 0u;

                const int nval = M - base;
                const uint32_t vmask = (nval >= 32) ? FULLM : ((1u << nval) - 1u);
                const uint32_t rem_w = __shfl_sync(FULLM, rem, w);
                const uint32_t cand  = (~rem_w) & vmask;
                const uint32_t d = sdiag[base + lane] & above;

                // Jacobi fixpoint -> exact greedy decisions within this word
                uint32_t kept = cand;
                for (;;) {
                    const uint32_t contrib = (kept & (1u << lane)) ? d : 0u;
                    const uint32_t sup = __reduce_or_sync(FULLM, contrib);
                    const uint32_t k2 = cand & ~sup;
                    if (k2 == kept) break;
                    kept = k2;
                }
                if (lane == 0) s_keepw[w] = kept;

                // branch-free OR of kept rows into removed state
                uint32_t acc = 0u;
                #pragma unroll
                for (int b = 0; b < 32; ++b)
                    acc |= (kept & (1u << b)) ? r[b] : 0u;
                rem |= acc;
            }
        }
        __syncthreads();

        for (int i = tid; i < M; i += BLK) {
            if ((s_keepw[i >> 5] >> (i & 31)) & 1u) {
                const float4 bi = g_bx[i];
                out[i * 5 + 0] = g_sc[i];
                out[i * 5 + 1] = bi.x;
                out[i * 5 + 2] = bi.y;
                out[i * 5 + 3] = __fsub_rn(bi.z, bi.x);
                out[i * 5 + 4] = __fsub_rn(bi.w, bi.y);
                if (wk) out[5 * NN + i] = 1.0f;
            }
        }
    } else if (M > MAXM) {
        // correct-but-slow fallback (never expected: seed-fixed M ~ 922)
        for (int t = tid; t < NN / 32; t += BLK) s_kb[t] = 0u;
        __syncthreads();
        if (tid == 0) {
            for (int i = 0; i < M; ++i) {
                const float4 bi = g_bx[i];
                const float  ai = __fmul_rn(__fsub_rn(bi.z, bi.x), __fsub_rn(bi.w, bi.y));
                bool sup = false;
                for (int j = 0; j < i && !sup; ++j)
                    if ((s_kb[j >> 5] >> (j & 31)) & 1u)
                        sup = iou_gt(bi, ai, g_bx[j]);
                if (!sup) {
                    s_kb[i >> 5] |= 1u << (i & 31);
                    out[i * 5 + 0] = g_sc[i];
                    out[i * 5 + 1] = bi.x;
                    out[i * 5 + 2] = bi.y;
                    out[i * 5 + 3] = __fsub_rn(bi.z, bi.x);
                    out[i * 5 + 4] = __fsub_rn(bi.w, bi.y);
                    if (wk) out[5 * NN + i] = 1.0f;
                }
            }
        }
        __syncthreads();
    }

    // deterministic state for the next graph replay
    if (tid == 0) { g_cnt = 0; g_bar_flag = 0; }
}

// ---------------------------------------------------------------------------
extern "C" void kernel_launch(void* const* d_in, const int* in_sizes, int n_in,
                              void* d_out, int out_size)
{
    const float* x = (const float*)d_in[0];
    float* out = (float*)d_out;
    k_all<<<GRID, BLK>>>(x, out, out_size);
}